// round 11
// baseline (speedup 1.0000x reference)
#include <cuda_runtime.h>
#include <cstdint>

// GatedDeltaRuleModule: 5-tap causal local attention. B=2, S=8192, H=16, D=128, W=4.
// out[b,s,h,:] = sum_{d=0..4} (q_s . k_{s-d}) * scale * sigmoid(a_s * b_{s-d}) * v_{s-d}
// out[b,0,h,:] = v[b,0,h,:]
//
// R10 = R9 (warp-strip streaming + per-warp cp.async ring, k/v history in a
// rolling register window) with two targeted changes:
//  - CH 64 -> 32: grid 1024 -> 2048 blocks. R9 was GRID-capped at 6.92 blocks/SM
//    (occ 37%); now 8 blocks/SM resident (full 64K-reg RF) -> 32 warps/SM.
//  - sigmoid via tanh.approx.f32 (1 MUFU instead of EX2+RCP): ~10 fewer
//    instr/row, halves MUFU pipe pressure. Error ~1e-4 << 1e-3 tolerance.

#define BATCH 2
#define SEQ   8192
#define HEADS 16
#define DIM   128
#define WIN   4
#define CH    32
#define THREADS 128
#define WPB   4
#define CHUNKS (SEQ / CH)                       // 256
#define NBLOCKS (BATCH * HEADS * CHUNKS / WPB)  // 2048
#define NSLOT 4
#define PIPE  3                                 // cp.async groups in flight
#define SLOT_FLOATS (3 * DIM)                   // q|k|v row = 1536 B

struct WarpSmem {
    float ring[NSLOT][SLOT_FLOATS];  // [0..127]=q, [128..255]=k, [256..383]=v
    float ash[CH];
    float bsh[CH + WIN];             // bsh[j] = b[s0-4+j]
};

__device__ __forceinline__ float dot4(const float4 a, const float4 b) {
    return a.x * b.x + a.y * b.y + a.z * b.z + a.w * b.w;
}

__device__ __forceinline__ void cp16(uint32_t saddr, const float* g) {
    asm volatile("cp.async.cg.shared.global [%0], [%1], 16;" :: "r"(saddr), "l"(g));
}

// sigmoid(x) = 0.5*tanh(0.5x) + 0.5  (single MUFU.TANH, ~1e-4 abs err)
__device__ __forceinline__ float sigmoid_tanh(float x) {
    float t;
    asm("tanh.approx.f32 %0, %1;" : "=f"(t) : "f"(0.5f * x));
    return fmaf(0.5f, t, 0.5f);
}

__global__ __launch_bounds__(THREADS, 8)
void gdr_pipe_kernel(const float* __restrict__ q,
                     const float* __restrict__ k,
                     const float* __restrict__ v,
                     const float* __restrict__ a,
                     const float* __restrict__ b,
                     float* __restrict__ out)
{
    __shared__ WarpSmem wsm[WPB];

    const int lane = threadIdx.x & 31;
    const int wid  = threadIdx.x >> 5;
    const int wg   = blockIdx.x * WPB + wid;

    const int chunk = wg & (CHUNKS - 1);          // bits 0..7
    const int h     = (wg >> 8) & (HEADS - 1);    // bits 8..11
    const int bb    = wg >> 12;                   // bit 12
    const int s0    = chunk * CH;

    const float  SCALE     = 0.08838834764831845f;  // 1/sqrt(128)
    const size_t ROWSTRIDE = (size_t)HEADS * DIM;   // 2048 floats

    WarpSmem& S = wsm[wid];
    const size_t off0 = (((size_t)bb * SEQ + s0) * HEADS + h) * DIM;
    const float* qp = q + off0 + lane * 4;
    const float* kp = k + off0 + lane * 4;
    const float* vp = v + off0 + lane * 4;
    float*       op = out + off0 + lane * 4;
    const uint32_t ring0 =
        (uint32_t)__cvta_generic_to_shared(&S.ring[0][0]) + (uint32_t)(lane * 16);

    // ---- a/b strip preload into warp-private smem (gate path off DRAM latency) ----
    for (int j = lane; j < CH + WIN; j += 32) {
        const int s = s0 - WIN + j;
        S.bsh[j] = (s >= 0) ? b[((size_t)bb * SEQ + s) * HEADS + h] : 0.f;
    }
    if (lane < CH)
        S.ash[lane] = a[((size_t)bb * SEQ + (s0 + lane)) * HEADS + h];

    // ---- k/v halo window (rows s0-1..s0-4); zero for s0==0, matching padding ----
    const float4 z4 = make_float4(0.f, 0.f, 0.f, 0.f);
    float4 k1 = z4, k2 = z4, k3 = z4, k4 = z4;
    float4 v1 = z4, v2 = z4, v3 = z4, v4 = z4;
    if (s0 != 0) {  // s0 multiple of CH=32 => all 4 halo rows exist
        k1 = *reinterpret_cast<const float4*>(kp - 1 * ROWSTRIDE);
        v1 = *reinterpret_cast<const float4*>(vp - 1 * ROWSTRIDE);
        k2 = *reinterpret_cast<const float4*>(kp - 2 * ROWSTRIDE);
        v2 = *reinterpret_cast<const float4*>(vp - 2 * ROWSTRIDE);
        k3 = *reinterpret_cast<const float4*>(kp - 3 * ROWSTRIDE);
        v3 = *reinterpret_cast<const float4*>(vp - 3 * ROWSTRIDE);
        k4 = *reinterpret_cast<const float4*>(kp - 4 * ROWSTRIDE);
        v4 = *reinterpret_cast<const float4*>(vp - 4 * ROWSTRIDE);
    }

    __syncwarp();  // cross-lane reads of ash/bsh in the loop

    // ---- Pipeline prologue: stage rows 0..PIPE-1 (one commit group per row) ----
#pragma unroll
    for (int i = 0; i < PIPE; i++) {
        const uint32_t dst = ring0 + (uint32_t)((i & (NSLOT - 1)) * SLOT_FLOATS * 4);
        cp16(dst,               qp + (size_t)i * ROWSTRIDE);
        cp16(dst + DIM * 4,     kp + (size_t)i * ROWSTRIDE);
        cp16(dst + 2 * DIM * 4, vp + (size_t)i * ROWSTRIDE);
        asm volatile("cp.async.commit_group;" ::: "memory");
    }

    const bool first_chunk = (s0 == 0);

#pragma unroll 4
    for (int i = 0; i < CH; ++i) {
        // Completed groups >= (PIPE + i) - 2 = i+1  ->  row i's data has landed.
        asm volatile("cp.async.wait_group 2;" ::: "memory");

        const int slot = i & (NSLOT - 1);
        // Each lane reads exactly the 16B it staged itself: no syncwarp needed.
        const float4 cq = *reinterpret_cast<const float4*>(&S.ring[slot][lane * 4]);
        const float4 ck = *reinterpret_cast<const float4*>(&S.ring[slot][DIM + lane * 4]);
        const float4 cv = *reinterpret_cast<const float4*>(&S.ring[slot][2 * DIM + lane * 4]);

        // Stage row i+PIPE into slot (i+3)&3 == (i-1)&3 — consumed last iteration,
        // its LDS long retired: no smem write-after-read hazard.
        if (i + PIPE < CH) {
            const uint32_t dst =
                ring0 + (uint32_t)(((i + PIPE) & (NSLOT - 1)) * SLOT_FLOATS * 4);
            cp16(dst,               qp + (size_t)(i + PIPE) * ROWSTRIDE);
            cp16(dst + DIM * 4,     kp + (size_t)(i + PIPE) * ROWSTRIDE);
            cp16(dst + 2 * DIM * 4, vp + (size_t)(i + PIPE) * ROWSTRIDE);
        }
        asm volatile("cp.async.commit_group;" ::: "memory");  // keep group count uniform

        // 5 per-lane dot partials
        float p0 = dot4(cq, ck);
        float p1 = dot4(cq, k1);
        float p2 = dot4(cq, k2);
        float p3 = dot4(cq, k3);
        float p4 = dot4(cq, k4);

        // Full-warp butterfly, 5 taps interleaved (25 SHFL)
#pragma unroll
        for (int offx = 16; offx > 0; offx >>= 1) {
            p0 += __shfl_xor_sync(0xffffffffu, p0, offx);
            p1 += __shfl_xor_sync(0xffffffffu, p1, offx);
            p2 += __shfl_xor_sync(0xffffffffu, p2, offx);
            p3 += __shfl_xor_sync(0xffffffffu, p3, offx);
            p4 += __shfl_xor_sync(0xffffffffu, p4, offx);
        }

        // Gates from smem (LDS broadcast). bsh[i+4-d] = b[s-d]; halo rows are
        // zero-filled so p==0 there, matching the reference's zero-padding.
        const float ca = S.ash[i];
        const float c0 = p0 * SCALE * sigmoid_tanh(ca * S.bsh[i + 4]);
        const float c1 = p1 * SCALE * sigmoid_tanh(ca * S.bsh[i + 3]);
        const float c2 = p2 * SCALE * sigmoid_tanh(ca * S.bsh[i + 2]);
        const float c3 = p3 * SCALE * sigmoid_tanh(ca * S.bsh[i + 1]);
        const float c4 = p4 * SCALE * sigmoid_tanh(ca * S.bsh[i + 0]);

        float4 acc;
        acc.x = c0 * cv.x + c1 * v1.x + c2 * v2.x + c3 * v3.x + c4 * v4.x;
        acc.y = c0 * cv.y + c1 * v1.y + c2 * v2.y + c3 * v3.y + c4 * v4.y;
        acc.z = c0 * cv.z + c1 * v1.z + c2 * v2.z + c3 * v3.z + c4 * v4.z;
        acc.w = c0 * cv.w + c1 * v1.w + c2 * v2.w + c3 * v3.w + c4 * v4.w;

        if (first_chunk && i == 0)  // reference special-cases s==0: out = v_0
            acc = cv;

        *reinterpret_cast<float4*>(op + (size_t)i * ROWSTRIDE) = acc;

        // Slide history window (renamed under unroll-4: shift period matches)
        k4 = k3; k3 = k2; k2 = k1; k1 = ck;
        v4 = v3; v3 = v2; v2 = v1; v1 = cv;
    }
}

extern "C" void kernel_launch(void* const* d_in, const int* in_sizes, int n_in,
                              void* d_out, int out_size)
{
    const float* q = (const float*)d_in[0];
    const float* k = (const float*)d_in[1];
    const float* v = (const float*)d_in[2];
    const float* a = (const float*)d_in[3];
    const float* b = (const float*)d_in[4];
    float* out = (float*)d_out;

    gdr_pipe_kernel<<<NBLOCKS, THREADS>>>(q, k, v, a, b, out);
}

// round 12
// speedup vs baseline: 1.0232x; 1.0232x over previous
#include <cuda_runtime.h>
#include <cstdint>

// GatedDeltaRuleModule: 5-tap causal local attention. B=2, S=8192, H=16, D=128, W=4.
// out[b,s,h,:] = sum_{d=0..4} (q_s . k_{s-d}) * scale * sigmoid(a_s * b_{s-d}) * v_{s-d}
// out[b,0,h,:] = v[b,0,h,:]
//
// R12 = R11 core (warp-strip streaming, per-warp cp.async ring PIPE=3, k/v
// history in a rolling register window, tanh-based sigmoid) with PERSISTENT
// scheduling: grid = 1184 blocks (exactly 8/SM, single wave); warps pull
// 32-row chunks from a global atomic ticket. Eliminates the 2-wave tail
// (43 us at 73% residency) that capped DRAM at 69.5%. Output is independent
// of warp<->chunk assignment (chunks disjoint), so determinism holds.

#define BATCH 2
#define SEQ   8192
#define HEADS 16
#define DIM   128
#define WIN   4
#define CH    32
#define THREADS 128
#define WPB   4
#define CHUNKS (SEQ / CH)                        // 256
#define TOTAL_CHUNKS (BATCH * HEADS * CHUNKS)    // 8192
#define NBLOCKS (148 * 8)                        // 1184: exactly 8 blocks/SM
#define NSLOT 4
#define PIPE  3
#define SLOT_FLOATS (3 * DIM)                    // q|k|v row = 1536 B

__device__ unsigned g_ticket;

__global__ void gdr_reset_ticket() { g_ticket = 0u; }

struct WarpSmem {
    float ring[NSLOT][SLOT_FLOATS];  // [0..127]=q, [128..255]=k, [256..383]=v
    float ash[CH];
    float bsh[CH + WIN];             // bsh[j] = b[s0-4+j]
};

__device__ __forceinline__ float dot4(const float4 a, const float4 b) {
    return a.x * b.x + a.y * b.y + a.z * b.z + a.w * b.w;
}

__device__ __forceinline__ void cp16(uint32_t saddr, const float* g) {
    asm volatile("cp.async.cg.shared.global [%0], [%1], 16;" :: "r"(saddr), "l"(g));
}

// sigmoid(x) = 0.5*tanh(0.5x) + 0.5  (single MUFU.TANH, ~1e-4 abs err)
__device__ __forceinline__ float sigmoid_tanh(float x) {
    float t;
    asm("tanh.approx.f32 %0, %1;" : "=f"(t) : "f"(0.5f * x));
    return fmaf(0.5f, t, 0.5f);
}

__global__ __launch_bounds__(THREADS, 8)
void gdr_persist_kernel(const float* __restrict__ q,
                        const float* __restrict__ k,
                        const float* __restrict__ v,
                        const float* __restrict__ a,
                        const float* __restrict__ b,
                        float* __restrict__ out)
{
    __shared__ WarpSmem wsm[WPB];

    const int lane = threadIdx.x & 31;
    const int wid  = threadIdx.x >> 5;
    WarpSmem& S = wsm[wid];

    const float  SCALE     = 0.08838834764831845f;  // 1/sqrt(128)
    const size_t ROWSTRIDE = (size_t)HEADS * DIM;   // 2048 floats
    const uint32_t ring0 =
        (uint32_t)__cvta_generic_to_shared(&S.ring[0][0]) + (uint32_t)(lane * 16);

    for (;;) {
        // ---- Pull next chunk from the global ticket (warp-granular) ----
        unsigned t;
        if (lane == 0) t = atomicAdd(&g_ticket, 1u);
        t = __shfl_sync(0xffffffffu, t, 0);
        if (t >= TOTAL_CHUNKS) break;

        const int chunk = t & (CHUNKS - 1);          // bits 0..7
        const int h     = (t >> 8) & (HEADS - 1);    // bits 8..11
        const int bb    = (int)(t >> 12);            // bit 12
        const int s0    = chunk * CH;

        const size_t off0 = (((size_t)bb * SEQ + s0) * HEADS + h) * DIM;
        const float* qp = q + off0 + lane * 4;
        const float* kp = k + off0 + lane * 4;
        const float* vp = v + off0 + lane * 4;
        float*       op = out + off0 + lane * 4;

        // Protect previous chunk's cross-lane bsh/ash reads before overwriting.
        __syncwarp();

        // ---- a/b strip preload into warp-private smem ----
        for (int j = lane; j < CH + WIN; j += 32) {
            const int s = s0 - WIN + j;
            S.bsh[j] = (s >= 0) ? b[((size_t)bb * SEQ + s) * HEADS + h] : 0.f;
        }
        S.ash[lane] = a[((size_t)bb * SEQ + (s0 + lane)) * HEADS + h];  // CH==32

        // ---- k/v halo window (rows s0-1..s0-4); zero for s0==0 (padding) ----
        const float4 z4 = make_float4(0.f, 0.f, 0.f, 0.f);
        float4 k1 = z4, k2 = z4, k3 = z4, k4 = z4;
        float4 v1 = z4, v2 = z4, v3 = z4, v4 = z4;
        if (s0 != 0) {  // s0 multiple of CH=32 => all 4 halo rows exist
            k1 = *reinterpret_cast<const float4*>(kp - 1 * ROWSTRIDE);
            v1 = *reinterpret_cast<const float4*>(vp - 1 * ROWSTRIDE);
            k2 = *reinterpret_cast<const float4*>(kp - 2 * ROWSTRIDE);
            v2 = *reinterpret_cast<const float4*>(vp - 2 * ROWSTRIDE);
            k3 = *reinterpret_cast<const float4*>(kp - 3 * ROWSTRIDE);
            v3 = *reinterpret_cast<const float4*>(vp - 3 * ROWSTRIDE);
            k4 = *reinterpret_cast<const float4*>(kp - 4 * ROWSTRIDE);
            v4 = *reinterpret_cast<const float4*>(vp - 4 * ROWSTRIDE);
        }

        __syncwarp();  // ash/bsh visible to all lanes

        // ---- Pipeline prologue: stage rows 0..PIPE-1 ----
#pragma unroll
        for (int i = 0; i < PIPE; i++) {
            const uint32_t dst = ring0 + (uint32_t)((i & (NSLOT - 1)) * SLOT_FLOATS * 4);
            cp16(dst,               qp + (size_t)i * ROWSTRIDE);
            cp16(dst + DIM * 4,     kp + (size_t)i * ROWSTRIDE);
            cp16(dst + 2 * DIM * 4, vp + (size_t)i * ROWSTRIDE);
            asm volatile("cp.async.commit_group;" ::: "memory");
        }

        const bool first_chunk = (s0 == 0);

#pragma unroll 4
        for (int i = 0; i < CH; ++i) {
            // Completed groups >= i+1 -> row i's data has landed (leftover empty
            // groups from the previous chunk drain here too).
            asm volatile("cp.async.wait_group 2;" ::: "memory");

            const int slot = i & (NSLOT - 1);
            // Each lane reads exactly the 16B it staged itself: no syncwarp.
            const float4 cq = *reinterpret_cast<const float4*>(&S.ring[slot][lane * 4]);
            const float4 ck = *reinterpret_cast<const float4*>(&S.ring[slot][DIM + lane * 4]);
            const float4 cv = *reinterpret_cast<const float4*>(&S.ring[slot][2 * DIM + lane * 4]);

            // Stage row i+PIPE into slot (i-1)&3 — consumed last iteration.
            if (i + PIPE < CH) {
                const uint32_t dst =
                    ring0 + (uint32_t)(((i + PIPE) & (NSLOT - 1)) * SLOT_FLOATS * 4);
                cp16(dst,               qp + (size_t)(i + PIPE) * ROWSTRIDE);
                cp16(dst + DIM * 4,     kp + (size_t)(i + PIPE) * ROWSTRIDE);
                cp16(dst + 2 * DIM * 4, vp + (size_t)(i + PIPE) * ROWSTRIDE);
            }
            asm volatile("cp.async.commit_group;" ::: "memory");  // uniform group count

            // 5 per-lane dot partials
            float p0 = dot4(cq, ck);
            float p1 = dot4(cq, k1);
            float p2 = dot4(cq, k2);
            float p3 = dot4(cq, k3);
            float p4 = dot4(cq, k4);

            // Full-warp butterfly, 5 taps interleaved (25 SHFL)
#pragma unroll
            for (int offx = 16; offx > 0; offx >>= 1) {
                p0 += __shfl_xor_sync(0xffffffffu, p0, offx);
                p1 += __shfl_xor_sync(0xffffffffu, p1, offx);
                p2 += __shfl_xor_sync(0xffffffffu, p2, offx);
                p3 += __shfl_xor_sync(0xffffffffu, p3, offx);
                p4 += __shfl_xor_sync(0xffffffffu, p4, offx);
            }

            // Gates from smem (LDS broadcast). bsh[i+4-d] = b[s-d]; halo rows
            // zero-filled -> p==0 there, matching the reference's zero-padding.
            const float ca = S.ash[i];
            const float c0 = p0 * SCALE * sigmoid_tanh(ca * S.bsh[i + 4]);
            const float c1 = p1 * SCALE * sigmoid_tanh(ca * S.bsh[i + 3]);
            const float c2 = p2 * SCALE * sigmoid_tanh(ca * S.bsh[i + 2]);
            const float c3 = p3 * SCALE * sigmoid_tanh(ca * S.bsh[i + 1]);
            const float c4 = p4 * SCALE * sigmoid_tanh(ca * S.bsh[i + 0]);

            float4 acc;
            acc.x = c0 * cv.x + c1 * v1.x + c2 * v2.x + c3 * v3.x + c4 * v4.x;
            acc.y = c0 * cv.y + c1 * v1.y + c2 * v2.y + c3 * v3.y + c4 * v4.y;
            acc.z = c0 * cv.z + c1 * v1.z + c2 * v2.z + c3 * v3.z + c4 * v4.z;
            acc.w = c0 * cv.w + c1 * v1.w + c2 * v2.w + c3 * v3.w + c4 * v4.w;

            if (first_chunk && i == 0)  // reference special-cases s==0: out = v_0
                acc = cv;

            // Streaming store: out is never re-read.
            __stcs(reinterpret_cast<float4*>(op + (size_t)i * ROWSTRIDE), acc);

            // Slide history window (renamed under unroll-4)
            k4 = k3; k3 = k2; k2 = k1; k1 = ck;
            v4 = v3; v3 = v2; v2 = v1; v1 = cv;
        }
    }
}

extern "C" void kernel_launch(void* const* d_in, const int* in_sizes, int n_in,
                              void* d_out, int out_size)
{
    const float* q = (const float*)d_in[0];
    const float* k = (const float*)d_in[1];
    const float* v = (const float*)d_in[2];
    const float* a = (const float*)d_in[3];
    const float* b = (const float*)d_in[4];
    float* out = (float*)d_out;

    gdr_reset_ticket<<<1, 1>>>();
    gdr_persist_kernel<<<NBLOCKS, THREADS>>>(q, k, v, a, b, out);
}